// round 1
// baseline (speedup 1.0000x reference)
#include <cuda_runtime.h>
#include <cuda_bf16.h>

// Problem constants (fixed by setup_inputs): N=512, A=1024, B=64, C=16
#define NN   512
#define AA   1024
#define BB   64
#define CC   16
#define OUTW (AA + BB)   // 1088

// Scratch for M = x @ T.reshape(A, B*C)  -> (512, 1024) fp32 = 2 MB
__device__ float g_M[NN * AA];

// ---------------------------------------------------------------------------
// Kernel 1: copy x into out[:, 0:1024]  (float4 vectorized)
// grid: (512), block: (256)  -> each thread one float4 of the row
// ---------------------------------------------------------------------------
__global__ void copy_x_kernel(const float* __restrict__ x, float* __restrict__ out) {
    int i = blockIdx.x;
    int t = threadIdx.x;                     // 0..255, 256*4 = 1024 floats
    float4 v = reinterpret_cast<const float4*>(x + (size_t)i * AA)[t];
    reinterpret_cast<float4*>(out + (size_t)i * OUTW)[t] = v;
}

// ---------------------------------------------------------------------------
// Kernel 2: GEMM  M = x (512x1024) @ W (1024x1024), fp32
// Block tile 64x64, K-tile 16, 256 threads, 4x4 microtile.
// grid: (16 col-tiles, 8 row-tiles) = 128 blocks (one wave on 148 SMs)
// ---------------------------------------------------------------------------
__global__ __launch_bounds__(256, 2)
void gemm_kernel(const float* __restrict__ A, const float* __restrict__ W) {
    __shared__ float As[16][65];   // [k][m], padded to kill store conflicts
    __shared__ float Bs[16][64];   // [k][n]

    const int tid = threadIdx.x;
    const int tx  = tid & 15;      // 0..15 -> n microtile
    const int ty  = tid >> 4;      // 0..15 -> m microtile
    const int row0 = blockIdx.y * 64;
    const int col0 = blockIdx.x * 64;

    float acc[4][4];
#pragma unroll
    for (int m = 0; m < 4; m++)
#pragma unroll
        for (int n = 0; n < 4; n++) acc[m][n] = 0.0f;

    for (int k0 = 0; k0 < AA; k0 += 16) {
        // Load A tile: 64 rows x 16 k  (1024 elems / 256 threads = 4 each)
#pragma unroll
        for (int it = 0; it < 4; it++) {
            int e  = tid + it * 256;
            int r  = e >> 4;          // 0..63
            int kk = e & 15;          // 0..15
            As[kk][r] = A[(size_t)(row0 + r) * AA + k0 + kk];
        }
        // Load B tile: 16 k x 64 cols
#pragma unroll
        for (int it = 0; it < 4; it++) {
            int e  = tid + it * 256;
            int kk = e >> 6;          // 0..15
            int c  = e & 63;          // 0..63
            Bs[kk][c] = W[(size_t)(k0 + kk) * AA + col0 + c];
        }
        __syncthreads();

#pragma unroll
        for (int kk = 0; kk < 16; kk++) {
            float a[4], b[4];
#pragma unroll
            for (int q = 0; q < 4; q++) a[q] = As[kk][ty * 4 + q];
#pragma unroll
            for (int q = 0; q < 4; q++) b[q] = Bs[kk][tx * 4 + q];
#pragma unroll
            for (int m = 0; m < 4; m++)
#pragma unroll
                for (int n = 0; n < 4; n++)
                    acc[m][n] = fmaf(a[m], b[n], acc[m][n]);
        }
        __syncthreads();
    }

    // Write 4x4 microtile, float4 per row
#pragma unroll
    for (int m = 0; m < 4; m++) {
        float4 v = make_float4(acc[m][0], acc[m][1], acc[m][2], acc[m][3]);
        reinterpret_cast<float4*>(
            g_M + (size_t)(row0 + ty * 4 + m) * AA + col0 + tx * 4)[0] = v;
    }
}

// ---------------------------------------------------------------------------
// Kernel 3: pairwise L1 + exp-sum.
//   out[i, 1024+b] = sum_j exp(-sum_c |M[i,b,c]-M[j,b,c]|) - 1
// Block handles ITILE=4 consecutive i's -> 128 blocks.
// Thread layout: b = tid & 63, g = tid >> 6 (j partitioned over 4 groups).
// ---------------------------------------------------------------------------
#define ITILE 4

__global__ __launch_bounds__(256, 2)
void pairwise_kernel(float* __restrict__ out) {
    const int b  = threadIdx.x & 63;
    const int g  = threadIdx.x >> 6;          // 0..3
    const int i0 = blockIdx.x * ITILE;

    // Cache M[i, b*16 .. b*16+16) for the 4 i's in registers
    float mi[ITILE][CC];
#pragma unroll
    for (int ii = 0; ii < ITILE; ii++) {
        const float4* p = reinterpret_cast<const float4*>(
            g_M + (size_t)(i0 + ii) * AA + b * CC);
        float4 v0 = p[0], v1 = p[1], v2 = p[2], v3 = p[3];
        mi[ii][0]  = v0.x; mi[ii][1]  = v0.y; mi[ii][2]  = v0.z; mi[ii][3]  = v0.w;
        mi[ii][4]  = v1.x; mi[ii][5]  = v1.y; mi[ii][6]  = v1.z; mi[ii][7]  = v1.w;
        mi[ii][8]  = v2.x; mi[ii][9]  = v2.y; mi[ii][10] = v2.z; mi[ii][11] = v2.w;
        mi[ii][12] = v3.x; mi[ii][13] = v3.y; mi[ii][14] = v3.z; mi[ii][15] = v3.w;
    }

    float acc[ITILE];
#pragma unroll
    for (int ii = 0; ii < ITILE; ii++) acc[ii] = 0.0f;

    for (int j = g; j < NN; j += 4) {
        const float4* p = reinterpret_cast<const float4*>(
            g_M + (size_t)j * AA + b * CC);
        float4 v0 = p[0], v1 = p[1], v2 = p[2], v3 = p[3];
        float mj[CC];
        mj[0]  = v0.x; mj[1]  = v0.y; mj[2]  = v0.z; mj[3]  = v0.w;
        mj[4]  = v1.x; mj[5]  = v1.y; mj[6]  = v1.z; mj[7]  = v1.w;
        mj[8]  = v2.x; mj[9]  = v2.y; mj[10] = v2.z; mj[11] = v2.w;
        mj[12] = v3.x; mj[13] = v3.y; mj[14] = v3.z; mj[15] = v3.w;

#pragma unroll
        for (int ii = 0; ii < ITILE; ii++) {
            float s = 0.0f;
#pragma unroll
            for (int c = 0; c < CC; c++)
                s += fabsf(mi[ii][c] - mj[c]);
            acc[ii] += __expf(-s);
        }
    }

    // Reduce across the 4 g-groups per (ii, b)
    __shared__ float red[ITILE][4][BB];
#pragma unroll
    for (int ii = 0; ii < ITILE; ii++)
        red[ii][g][b] = acc[ii];
    __syncthreads();

    // thread (g, b) finalizes ii = g
    {
        int ii = g;
        float s = red[ii][0][b] + red[ii][1][b] + red[ii][2][b] + red[ii][3][b];
        out[(size_t)(i0 + ii) * OUTW + AA + b] = s - 1.0f;
    }
}

// ---------------------------------------------------------------------------
extern "C" void kernel_launch(void* const* d_in, const int* in_sizes, int n_in,
                              void* d_out, int out_size) {
    const float* x = (const float*)d_in[0];   // (512, 1024)
    const float* T = (const float*)d_in[1];   // (1024, 64, 16) == (1024, 1024)
    float* out = (float*)d_out;               // (512, 1088)

    copy_x_kernel<<<NN, 256>>>(x, out);

    dim3 ggrid(AA / 64, NN / 64);             // (16, 8)
    gemm_kernel<<<ggrid, 256>>>(x, T);

    pairwise_kernel<<<NN / ITILE, 256>>>(out);
}

// round 2
// speedup vs baseline: 1.4085x; 1.4085x over previous
#include <cuda_runtime.h>
#include <cuda_bf16.h>

// Problem constants (fixed by setup_inputs): N=512, A=1024, B=64, C=16
#define NN   512
#define AA   1024
#define BB   64
#define CC   16
#define OUTW (AA + BB)   // 1088

typedef unsigned long long ull;

// M transposed for coalesced pairwise loads:
// g_Mt[q][j][b] = float4 holding M[j, b*16 + q*4 .. +3]
__device__ float4 g_Mt[4 * NN * BB];
// Partial exp-sums per j-half: g_P[half][i*64 + b]
__device__ float g_P[2][NN * BB];

// ---------------- packed f32x2 helpers (sm_103a) ----------------
__device__ __forceinline__ ull pack2(float lo, float hi) {
    ull r; asm("mov.b64 %0, {%1,%2};" : "=l"(r) : "f"(lo), "f"(hi)); return r;
}
__device__ __forceinline__ ull add2(ull a, ull b) {
    ull r; asm("add.rn.f32x2 %0, %1, %2;" : "=l"(r) : "l"(a), "l"(b)); return r;
}
__device__ __forceinline__ ull fma2(ull a, ull b, ull c) {
    ull r; asm("fma.rn.f32x2 %0, %1, %2, %3;" : "=l"(r) : "l"(a), "l"(b), "l"(c)); return r;
}
__device__ __forceinline__ void unpack2(ull v, float& lo, float& hi) {
    asm("mov.b64 {%0,%1}, %2;" : "=f"(lo), "=f"(hi) : "l"(v));
}
#define ABS2_MASK  0x7FFFFFFF7FFFFFFFULL
#define NEG2_MASK  0x8000000080000000ULL

// ---------------------------------------------------------------------------
// Kernel 1: GEMM  M = x (512x1024) @ W (1024x1024), fp32, packed FFMA2.
// Block tile 64x64, K-tile 16, 256 threads, 4(m)x4(n) microtile (n packed 2x2).
// grid: (16 col-tiles, 8 row-tiles) = 128 blocks. Writes transposed g_Mt.
// ---------------------------------------------------------------------------
__global__ __launch_bounds__(256)
void gemm_kernel(const float* __restrict__ A, const float* __restrict__ W) {
    __shared__ float As[16][68];   // [k][m], stride 68 floats = 272B (16B-mult)
    __shared__ float Bs[16][64];   // [k][n]

    const int tid = threadIdx.x;
    const int tx  = tid & 15;      // n microtile
    const int ty  = tid >> 4;      // m microtile
    const int row0 = blockIdx.y * 64;
    const int col0 = blockIdx.x * 64;

    // global-load roles
    const int am  = tid >> 2;      // 0..63  (A row within tile)
    const int akq = tid & 3;       // 0..3   (k quad)
    const int bkk = tid >> 4;      // 0..15  (B k within tile)
    const int bcg = tid & 15;      // 0..15  (col quad)

    const float* aPtr = A + (size_t)(row0 + am) * AA + akq * 4;
    const float* wPtr = W + (size_t)bkk * AA + col0 + bcg * 4;

    ull acc2[4][2];
#pragma unroll
    for (int m = 0; m < 4; m++) { acc2[m][0] = 0ULL; acc2[m][1] = 0ULL; }

    float4 aReg = *reinterpret_cast<const float4*>(aPtr);
    float4 bReg = *reinterpret_cast<const float4*>(wPtr);

    for (int k0 = 0; k0 < AA; k0 += 16) {
        // stage current tiles
        As[akq * 4 + 0][am] = aReg.x;
        As[akq * 4 + 1][am] = aReg.y;
        As[akq * 4 + 2][am] = aReg.z;
        As[akq * 4 + 3][am] = aReg.w;
        *reinterpret_cast<float4*>(&Bs[bkk][bcg * 4]) = bReg;
        __syncthreads();

        // prefetch next tiles
        if (k0 + 16 < AA) {
            aReg = *reinterpret_cast<const float4*>(aPtr + (k0 + 16));
            bReg = *reinterpret_cast<const float4*>(wPtr + (size_t)(k0 + 16) * AA);
        }

#pragma unroll
        for (int kk = 0; kk < 16; kk++) {
            float4 av = *reinterpret_cast<const float4*>(&As[kk][ty * 4]);
            ull b01 = *reinterpret_cast<const ull*>(&Bs[kk][tx * 4]);
            ull b23 = *reinterpret_cast<const ull*>(&Bs[kk][tx * 4 + 2]);
            ull a0 = pack2(av.x, av.x);
            ull a1 = pack2(av.y, av.y);
            ull a2 = pack2(av.z, av.z);
            ull a3 = pack2(av.w, av.w);
            acc2[0][0] = fma2(a0, b01, acc2[0][0]);
            acc2[0][1] = fma2(a0, b23, acc2[0][1]);
            acc2[1][0] = fma2(a1, b01, acc2[1][0]);
            acc2[1][1] = fma2(a1, b23, acc2[1][1]);
            acc2[2][0] = fma2(a2, b01, acc2[2][0]);
            acc2[2][1] = fma2(a2, b23, acc2[2][1]);
            acc2[3][0] = fma2(a3, b01, acc2[3][0]);
            acc2[3][1] = fma2(a3, b23, acc2[3][1]);
        }
        __syncthreads();
    }

    // write to transposed layout: cols col0+tx*4..+3 -> (b, q)
    const int cq   = tx & 3;                       // which float4 (q) within b
    const int bidx = (col0 >> 4) + (tx >> 2);      // b index
#pragma unroll
    for (int m = 0; m < 4; m++) {
        float c0, c1, c2, c3;
        unpack2(acc2[m][0], c0, c1);
        unpack2(acc2[m][1], c2, c3);
        int row = row0 + ty * 4 + m;
        g_Mt[((size_t)cq * NN + row) * BB + bidx] = make_float4(c0, c1, c2, c3);
    }
}

// ---------------------------------------------------------------------------
// Kernel 2: pairwise L1 + exp-sum partials.
// grid (64 i-blocks, 2 j-halves), 256 threads = (b 0..63) x (g 0..3).
// Block handles ITILE=8 i's over its 256-j half; per thread 64 j iterations.
// ---------------------------------------------------------------------------
#define ITILE 8

__global__ __launch_bounds__(256)
void pairwise_kernel() {
    const int b  = threadIdx.x & 63;
    const int g  = threadIdx.x >> 6;          // 0..3
    const int i0 = blockIdx.x * ITILE;
    const int jh = blockIdx.y;                // 0..1

    // load -M[i, b*16..+16) packed (negated once so diff = add2(mj, nmi))
    ull nmi[ITILE][8];
#pragma unroll
    for (int ii = 0; ii < ITILE; ii++) {
#pragma unroll
        for (int q = 0; q < 4; q++) {
            float4 v = g_Mt[((size_t)q * NN + (i0 + ii)) * BB + b];
            nmi[ii][2 * q + 0] = pack2(v.x, v.y) ^ NEG2_MASK;
            nmi[ii][2 * q + 1] = pack2(v.z, v.w) ^ NEG2_MASK;
        }
    }

    float acc[ITILE];
#pragma unroll
    for (int ii = 0; ii < ITILE; ii++) acc[ii] = 0.0f;

    int j = jh * 256 + g;
    float4 pre[4];
#pragma unroll
    for (int q = 0; q < 4; q++)
        pre[q] = g_Mt[((size_t)q * NN + j) * BB + b];

    for (int it = 0; it < 64; it++) {
        float4 cur[4];
#pragma unroll
        for (int q = 0; q < 4; q++) cur[q] = pre[q];
        if (it + 1 < 64) {
            int jn = j + 4;
#pragma unroll
            for (int q = 0; q < 4; q++)
                pre[q] = g_Mt[((size_t)q * NN + jn) * BB + b];
        }

        ull mj[8];
#pragma unroll
        for (int q = 0; q < 4; q++) {
            mj[2 * q + 0] = pack2(cur[q].x, cur[q].y);
            mj[2 * q + 1] = pack2(cur[q].z, cur[q].w);
        }

#pragma unroll
        for (int ii = 0; ii < ITILE; ii++) {
            ull s2;
#pragma unroll
            for (int c = 0; c < 8; c++) {
                ull d = add2(mj[c], nmi[ii][c]) & ABS2_MASK;   // |mj - mi|
                s2 = (c == 0) ? d : add2(s2, d);
            }
            float lo, hi;
            unpack2(s2, lo, hi);
            acc[ii] += __expf(-(lo + hi));
        }
        j += 4;
    }

    // reduce over the 4 g-groups
    __shared__ float red[ITILE][4][BB];
#pragma unroll
    for (int ii = 0; ii < ITILE; ii++)
        red[ii][g][b] = acc[ii];
    __syncthreads();

    // 512 outputs, 256 threads -> 2 each (ii = g and g+4)
#pragma unroll
    for (int w = 0; w < 2; w++) {
        int ii = g + w * 4;
        float s = red[ii][0][b] + red[ii][1][b] + red[ii][2][b] + red[ii][3][b];
        g_P[jh][(size_t)(i0 + ii) * BB + b] = s;
    }
}

// ---------------------------------------------------------------------------
// Kernel 3: combine halves + copy x into out.
// grid 512 (one per row), 256 threads.
// ---------------------------------------------------------------------------
__global__ __launch_bounds__(256)
void combine_kernel(const float* __restrict__ x, float* __restrict__ out) {
    const int i = blockIdx.x;
    const int t = threadIdx.x;
    float4 v = reinterpret_cast<const float4*>(x + (size_t)i * AA)[t];
    reinterpret_cast<float4*>(out + (size_t)i * OUTW)[t] = v;
    if (t < BB) {
        float s = g_P[0][(size_t)i * BB + t] + g_P[1][(size_t)i * BB + t] - 1.0f;
        out[(size_t)i * OUTW + AA + t] = s;
    }
}

// ---------------------------------------------------------------------------
extern "C" void kernel_launch(void* const* d_in, const int* in_sizes, int n_in,
                              void* d_out, int out_size) {
    const float* x = (const float*)d_in[0];   // (512, 1024)
    const float* T = (const float*)d_in[1];   // (1024, 64, 16) == (1024, 1024)
    float* out = (float*)d_out;               // (512, 1088)

    dim3 ggrid(AA / 64, NN / 64);             // (16, 8) = 128 blocks
    gemm_kernel<<<ggrid, 256>>>(x, T);

    dim3 pgrid(NN / ITILE, 2);                // (64, 2) = 128 blocks
    pairwise_kernel<<<pgrid, 256>>>();

    combine_kernel<<<NN, 256>>>(x, out);
}

// round 4
// speedup vs baseline: 1.9529x; 1.3865x over previous
#include <cuda_runtime.h>
#include <cuda_bf16.h>
#include <cstdint>

// Problem constants: N=512, A=1024, B=64, C=16
#define NN   512
#define AA   1024
#define BB   64
#define CC   16
#define OUTW (AA + BB)   // 1088

typedef unsigned long long ull;

// ---------------- device scratch ----------------
// M transposed for coalesced pairwise loads: g_Mt[q][j][b] = float4 M[j, b*16+q*4 ..+3]
__device__ float4 g_Mt[4 * NN * BB];
__device__ float  g_P[2][NN * BB];          // partial exp-sums per j-half
__device__ __nv_bfloat16 g_xb[NN * AA];     // x in bf16
__device__ __nv_bfloat16 g_Wb[AA * AA];     // W transposed: g_Wb[n][k] = W[k][n], bf16

// ---------------- packed f32x2 helpers ----------------
__device__ __forceinline__ ull pack2(float lo, float hi) {
    ull r; asm("mov.b64 %0, {%1,%2};" : "=l"(r) : "f"(lo), "f"(hi)); return r;
}
__device__ __forceinline__ ull add2(ull a, ull b) {
    ull r; asm("add.rn.f32x2 %0, %1, %2;" : "=l"(r) : "l"(a), "l"(b)); return r;
}
__device__ __forceinline__ void unpack2(ull v, float& lo, float& hi) {
    asm("mov.b64 {%0,%1}, %2;" : "=f"(lo), "=f"(hi) : "l"(v));
}
#define ABS2_MASK  0x7FFFFFFF7FFFFFFFULL
#define NEG2_MASK  0x8000000080000000ULL

// ---------------- mma / ldmatrix helpers (family-compatible PTX) ----------------
__device__ __forceinline__ uint32_t smem_u32(const void* p) {
    uint32_t a;
    asm("{ .reg .u64 t; cvta.to.shared.u64 t, %1; cvt.u32.u64 %0, t; }" : "=r"(a) : "l"(p));
    return a;
}
#define LDMATRIX_X4(r0, r1, r2, r3, addr) \
    asm volatile("ldmatrix.sync.aligned.m8n8.x4.shared.b16 {%0,%1,%2,%3}, [%4];" \
        : "=r"(r0), "=r"(r1), "=r"(r2), "=r"(r3) : "r"(addr))

__device__ __forceinline__ void mma_bf16(float d[4], const uint32_t a[4], const uint32_t b[2]) {
    asm volatile(
        "mma.sync.aligned.m16n8k16.row.col.f32.bf16.bf16.f32 "
        "{%0,%1,%2,%3}, {%4,%5,%6,%7}, {%8,%9}, {%0,%1,%2,%3};"
        : "+f"(d[0]), "+f"(d[1]), "+f"(d[2]), "+f"(d[3])
        : "r"(a[0]), "r"(a[1]), "r"(a[2]), "r"(a[3]), "r"(b[0]), "r"(b[1]));
}

// ---------------------------------------------------------------------------
// Conversion kernels
// ---------------------------------------------------------------------------
__global__ __launch_bounds__(256)
void convert_x_kernel(const float* __restrict__ x) {
    int t = blockIdx.x * 256 + threadIdx.x;     // handles 8 floats
    const float4* src = reinterpret_cast<const float4*>(x) + 2 * (size_t)t;
    float4 a = src[0], b = src[1];
    __nv_bfloat162 p0 = __float22bfloat162_rn(make_float2(a.x, a.y));
    __nv_bfloat162 p1 = __float22bfloat162_rn(make_float2(a.z, a.w));
    __nv_bfloat162 p2 = __float22bfloat162_rn(make_float2(b.x, b.y));
    __nv_bfloat162 p3 = __float22bfloat162_rn(make_float2(b.z, b.w));
    uint4 out;
    out.x = *reinterpret_cast<uint32_t*>(&p0);
    out.y = *reinterpret_cast<uint32_t*>(&p1);
    out.z = *reinterpret_cast<uint32_t*>(&p2);
    out.w = *reinterpret_cast<uint32_t*>(&p3);
    reinterpret_cast<uint4*>(g_xb)[t] = out;
}

__global__ __launch_bounds__(256)
void convert_W_kernel(const float* __restrict__ W) {
    __shared__ float tile[32][33];
    const int n0 = blockIdx.x * 32;
    const int k0 = blockIdx.y * 32;
    const int tx = threadIdx.x & 31;
    const int ty = threadIdx.x >> 5;            // 0..7
#pragma unroll
    for (int r = 0; r < 4; r++)
        tile[ty + 8 * r][tx] = W[(size_t)(k0 + ty + 8 * r) * AA + n0 + tx];
    __syncthreads();
#pragma unroll
    for (int r = 0; r < 4; r++) {
        int n = n0 + ty + 8 * r;
        g_Wb[(size_t)n * AA + k0 + tx] = __float2bfloat16(tile[tx][ty + 8 * r]);
    }
}

// ---------------------------------------------------------------------------
// GEMM via mma.sync bf16 m16n8k16.
// Block: 64(m) x 64(n), 128 threads = 4 warps (2m x 2n), warp = 32x32.
// K chunked by 64; smem rows 128B with 16B-unit XOR swizzle (conflict-free
// ldmatrix + staging). grid (16 n-tiles, 8 m-tiles) = 128 blocks.
// Writes M in transposed g_Mt layout.
// ---------------------------------------------------------------------------
#define BK 64
#define NCH (AA / BK)   // 16

__global__ __launch_bounds__(128)
void gemm_mma_kernel() {
    __shared__ __align__(1024) __nv_bfloat16 sA[64 * BK];   // 8 KB
    __shared__ __align__(1024) __nv_bfloat16 sB[64 * BK];   // 8 KB

    const int tid = threadIdx.x;
    const int wid = tid >> 5;
    const int l   = tid & 31;
    const int mw  = wid & 1;        // warp m (0/1)
    const int nw  = wid >> 1;       // warp n (0/1)
    const int row0 = blockIdx.y * 64;
    const int col0 = blockIdx.x * 64;

    const uint32_t sA_addr = smem_u32(sA);
    const uint32_t sB_addr = smem_u32(sB);

    float acc[2][4][4];
#pragma unroll
    for (int mt = 0; mt < 2; mt++)
#pragma unroll
        for (int nt = 0; nt < 4; nt++)
#pragma unroll
            for (int e = 0; e < 4; e++) acc[mt][nt][e] = 0.0f;

    // staging roles: 4 segments per array; seg s: ch = tid + s*128, r=ch>>3, u=ch&7
    // prefetch chunk 0
    uint4 pa[4], pb[4];
#pragma unroll
    for (int s = 0; s < 4; s++) {
        int ch = tid + s * 128;
        int r = ch >> 3, u = ch & 7;
        pa[s] = *reinterpret_cast<const uint4*>(g_xb + (size_t)(row0 + r) * AA + u * 8);
        pb[s] = *reinterpret_cast<const uint4*>(g_Wb + (size_t)(col0 + r) * AA + u * 8);
    }

    // ldmatrix per-lane row bases (logical rows; phys unit = u ^ (row&7) = u ^ (l&7))
    // A, tile mt: row = mt*16 + ((l>>3)&1)*8 + (l&7); k-unit = ks*2 + (l>>4)
    // B, group ng: row = nw*32 + ng*16 + (l>>4)*8 + (l&7); k-unit = ks*2 + ((l>>3)&1)
    const int aRow0 = ((l >> 3) & 1) * 8 + (l & 7) + mw * 32;
    const int bRow0 = nw * 32 + ((l >> 4) << 3) + (l & 7);
    const int aKsel = (l >> 4);         // 0/1
    const int bKsel = ((l >> 3) & 1);   // 0/1
    const int swz   = (l & 7);

    for (int c = 0; c < NCH; c++) {
        // stage current chunk from prefetch regs
#pragma unroll
        for (int s = 0; s < 4; s++) {
            int ch = tid + s * 128;
            int r = ch >> 3, u = ch & 7;
            uint32_t off = (uint32_t)(r * 128 + ((u ^ (r & 7)) << 4));
            *reinterpret_cast<uint4*>(reinterpret_cast<char*>(sA) + off) = pa[s];
            *reinterpret_cast<uint4*>(reinterpret_cast<char*>(sB) + off) = pb[s];
        }
        __syncthreads();

        // prefetch next chunk (overlaps mma phase)
        if (c + 1 < NCH) {
            int k0 = (c + 1) * BK;
#pragma unroll
            for (int s = 0; s < 4; s++) {
                int ch = tid + s * 128;
                int r = ch >> 3, u = ch & 7;
                pa[s] = *reinterpret_cast<const uint4*>(g_xb + (size_t)(row0 + r) * AA + k0 + u * 8);
                pb[s] = *reinterpret_cast<const uint4*>(g_Wb + (size_t)(col0 + r) * AA + k0 + u * 8);
            }
        }

#pragma unroll
        for (int ks = 0; ks < 4; ks++) {
            uint32_t af[2][4], bf[4][2];
#pragma unroll
            for (int mt = 0; mt < 2; mt++) {
                int row = aRow0 + mt * 16;
                uint32_t u = (uint32_t)(ks * 2 + aKsel);
                uint32_t addr = sA_addr + (uint32_t)(row * 128) + (((u ^ swz)) << 4);
                LDMATRIX_X4(af[mt][0], af[mt][1], af[mt][2], af[mt][3], addr);
            }
#pragma unroll
            for (int ng = 0; ng < 2; ng++) {
                int row = bRow0 + ng * 16;
                uint32_t u = (uint32_t)(ks * 2 + bKsel);
                uint32_t addr = sB_addr + (uint32_t)(row * 128) + (((u ^ swz)) << 4);
                uint32_t r0, r1, r2, r3;
                LDMATRIX_X4(r0, r1, r2, r3, addr);
                bf[ng * 2 + 0][0] = r0; bf[ng * 2 + 0][1] = r1;
                bf[ng * 2 + 1][0] = r2; bf[ng * 2 + 1][1] = r3;
            }
#pragma unroll
            for (int mt = 0; mt < 2; mt++)
#pragma unroll
                for (int nt = 0; nt < 4; nt++)
                    mma_bf16(acc[mt][nt], af[mt], bf[nt]);
        }
        __syncthreads();
    }

    // Epilogue: write transposed g_Mt. Thread holds (rows g, g+8) x (cols 2c,2c+1) per tile.
    const int g = l >> 2;
    const int cc2 = (l & 3) * 2;
#pragma unroll
    for (int mt = 0; mt < 2; mt++) {
#pragma unroll
        for (int nt = 0; nt < 4; nt++) {
            int gcol = col0 + nw * 32 + nt * 8 + cc2;
            int q = (gcol >> 2) & 3;
            int b = gcol >> 4;
            int half = (gcol >> 1) & 1;
            int rowA = row0 + mw * 32 + mt * 16 + g;
            float2* p0 = reinterpret_cast<float2*>(&g_Mt[((size_t)q * NN + rowA) * BB + b]);
            p0[half] = make_float2(acc[mt][nt][0], acc[mt][nt][1]);
            float2* p1 = reinterpret_cast<float2*>(&g_Mt[((size_t)q * NN + rowA + 8) * BB + b]);
            p1[half] = make_float2(acc[mt][nt][2], acc[mt][nt][3]);
        }
    }
}

// ---------------------------------------------------------------------------
// Pairwise L1 + exp-sum partials, with exact early-exit.
// grid (64 i-blocks, 2 j-halves), 256 threads = (b 0..63) x (g 0..3).
// ---------------------------------------------------------------------------
#define ITILE 8
#define L1_SKIP 125.0f   // partial>125 => true l1 (ours AND fp32-ref) > 110 => exp == 0.0f

__global__ __launch_bounds__(256)
void pairwise_kernel() {
    const int b  = threadIdx.x & 63;
    const int g  = threadIdx.x >> 6;
    const int i0 = blockIdx.x * ITILE;
    const int jh = blockIdx.y;

    ull nmi[ITILE][8];
#pragma unroll
    for (int ii = 0; ii < ITILE; ii++) {
#pragma unroll
        for (int q = 0; q < 4; q++) {
            float4 v = g_Mt[((size_t)q * NN + (i0 + ii)) * BB + b];
            nmi[ii][2 * q + 0] = pack2(v.x, v.y) ^ NEG2_MASK;
            nmi[ii][2 * q + 1] = pack2(v.z, v.w) ^ NEG2_MASK;
        }
    }

    float acc[ITILE];
#pragma unroll
    for (int ii = 0; ii < ITILE; ii++) acc[ii] = 0.0f;

    int j = jh * 256 + g;
    float4 pre[4];
#pragma unroll
    for (int q = 0; q < 4; q++)
        pre[q] = g_Mt[((size_t)q * NN + j) * BB + b];

    for (int it = 0; it < 64; it++) {
        float4 cur[4];
#pragma unroll
        for (int q = 0; q < 4; q++) cur[q] = pre[q];
        if (it + 1 < 64) {
            int jn = j + 4;
#pragma unroll
            for (int q = 0; q < 4; q++)
                pre[q] = g_Mt[((size_t)q * NN + jn) * BB + b];
        }

        ull mj[8];
#pragma unroll
        for (int q = 0; q < 4; q++) {
            mj[2 * q + 0] = pack2(cur[q].x, cur[q].y);
            mj[2 * q + 1] = pack2(cur[q].z, cur[q].w);
        }

        // first half (8 components) — lower bound on l1
        float part[ITILE];
        bool big = true;
#pragma unroll
        for (int ii = 0; ii < ITILE; ii++) {
            ull d0 = add2(mj[0], nmi[ii][0]) & ABS2_MASK;
            ull d1 = add2(mj[1], nmi[ii][1]) & ABS2_MASK;
            ull d2 = add2(mj[2], nmi[ii][2]) & ABS2_MASK;
            ull d3 = add2(mj[3], nmi[ii][3]) & ABS2_MASK;
            ull s = add2(add2(d0, d1), add2(d2, d3));
            float lo, hi; unpack2(s, lo, hi);
            part[ii] = lo + hi;
            big = big && (part[ii] > L1_SKIP);
        }
        if (!__all_sync(0xFFFFFFFFu, big)) {
#pragma unroll
            for (int ii = 0; ii < ITILE; ii++) {
                ull d4 = add2(mj[4], nmi[ii][4]) & ABS2_MASK;
                ull d5 = add2(mj[5], nmi[ii][5]) & ABS2_MASK;
                ull d6 = add2(mj[6], nmi[ii][6]) & ABS2_MASK;
                ull d7 = add2(mj[7], nmi[ii][7]) & ABS2_MASK;
                ull s = add2(add2(d4, d5), add2(d6, d7));
                float lo, hi; unpack2(s, lo, hi);
                acc[ii] += __expf(-(part[ii] + lo + hi));
            }
        }
        j += 4;
    }

    __shared__ float red[ITILE][4][BB];
#pragma unroll
    for (int ii = 0; ii < ITILE; ii++)
        red[ii][g][b] = acc[ii];
    __syncthreads();

#pragma unroll
    for (int w = 0; w < 2; w++) {
        int ii = g + w * 4;
        float s = red[ii][0][b] + red[ii][1][b] + red[ii][2][b] + red[ii][3][b];
        g_P[jh][(size_t)(i0 + ii) * BB + b] = s;
    }
}

// ---------------------------------------------------------------------------
// Combine halves + copy x into out.
// ---------------------------------------------------------------------------
__global__ __launch_bounds__(256)
void combine_kernel(const float* __restrict__ x, float* __restrict__ out) {
    const int i = blockIdx.x;
    const int t = threadIdx.x;
    float4 v = reinterpret_cast<const float4*>(x + (size_t)i * AA)[t];
    reinterpret_cast<float4*>(out + (size_t)i * OUTW)[t] = v;
    if (t < BB) {
        float s = g_P[0][(size_t)i * BB + t] + g_P[1][(size_t)i * BB + t] - 1.0f;
        out[(size_t)i * OUTW + AA + t] = s;
    }
}

// ---------------------------------------------------------------------------
extern "C" void kernel_launch(void* const* d_in, const int* in_sizes, int n_in,
                              void* d_out, int out_size) {
    const float* x = (const float*)d_in[0];   // (512, 1024)
    const float* T = (const float*)d_in[1];   // (1024, 1024)
    float* out = (float*)d_out;               // (512, 1088)

    convert_x_kernel<<<NN * AA / (256 * 8), 256>>>(x);   // 256 blocks
    dim3 wgrid(AA / 32, AA / 32);                         // (32, 32)
    convert_W_kernel<<<wgrid, 256>>>(T);

    dim3 ggrid(AA / 64, NN / 64);                         // (16, 8) = 128 blocks
    gemm_mma_kernel<<<ggrid, 128>>>();

    dim3 pgrid(NN / ITILE, 2);                            // (64, 2)
    pairwise_kernel<<<pgrid, 256>>>();

    combine_kernel<<<NN, 256>>>(x, out);
}

// round 5
// speedup vs baseline: 2.6637x; 1.3639x over previous
#include <cuda_runtime.h>
#include <cuda_bf16.h>
#include <cstdint>

// Problem constants: N=512, A=1024, B=64, C=16
#define NN   512
#define AA   1024
#define BB   64
#define CC   16
#define OUTW (AA + BB)   // 1088

#define NGRP   32            // row groups of 16
#define GSZ    16
#define NTILES (NGRP * (NGRP + 1) / 2)   // 528

// ---------------- device scratch ----------------
// M in bf16x2, pairwise layout: g_Mb[row*512 + b*8 + c2], c2 = component-pair 0..7
__device__ uint32_t g_Mb[NN * 512];
// partial sums: g_Pp[src_group][row][b]; every slot written exactly once
__device__ float g_Pp[NGRP][NN * BB];
__device__ __nv_bfloat16 g_xb[NN * AA];     // x in bf16
__device__ __nv_bfloat16 g_Wb[AA * AA];     // W transposed: g_Wb[n][k] = W[k][n]

// ---------------- helpers ----------------
__device__ __forceinline__ uint32_t smem_u32(const void* p) {
    uint32_t a;
    asm("{ .reg .u64 t; cvta.to.shared.u64 t, %1; cvt.u32.u64 %0, t; }" : "=r"(a) : "l"(p));
    return a;
}
#define LDMATRIX_X4(r0, r1, r2, r3, addr) \
    asm volatile("ldmatrix.sync.aligned.m8n8.x4.shared.b16 {%0,%1,%2,%3}, [%4];" \
        : "=r"(r0), "=r"(r1), "=r"(r2), "=r"(r3) : "r"(addr))

__device__ __forceinline__ void mma_bf16(float d[4], const uint32_t a[4], const uint32_t b[2]) {
    asm volatile(
        "mma.sync.aligned.m16n8k16.row.col.f32.bf16.bf16.f32 "
        "{%0,%1,%2,%3}, {%4,%5,%6,%7}, {%8,%9}, {%0,%1,%2,%3};"
        : "+f"(d[0]), "+f"(d[1]), "+f"(d[2]), "+f"(d[3])
        : "r"(a[0]), "r"(a[1]), "r"(a[2]), "r"(a[3]), "r"(b[0]), "r"(b[1]));
}

__device__ __forceinline__ __nv_bfloat162 u2b(uint32_t u) {
    return *reinterpret_cast<__nv_bfloat162*>(&u);
}
__device__ __forceinline__ uint32_t b2u(__nv_bfloat162 v) {
    return *reinterpret_cast<uint32_t*>(&v);
}

// L1 over 16 bf16 components held as 8 bf16x2 regs; exact lo/hi extraction.
__device__ __forceinline__ float l1_16(const uint32_t* mj, const uint32_t* mi) {
    __nv_bfloat162 d0 = __habs2(__hsub2(u2b(mj[0]), u2b(mi[0])));
    __nv_bfloat162 d1 = __habs2(__hsub2(u2b(mj[1]), u2b(mi[1])));
    __nv_bfloat162 d2 = __habs2(__hsub2(u2b(mj[2]), u2b(mi[2])));
    __nv_bfloat162 d3 = __habs2(__hsub2(u2b(mj[3]), u2b(mi[3])));
    __nv_bfloat162 d4 = __habs2(__hsub2(u2b(mj[4]), u2b(mi[4])));
    __nv_bfloat162 d5 = __habs2(__hsub2(u2b(mj[5]), u2b(mi[5])));
    __nv_bfloat162 d6 = __habs2(__hsub2(u2b(mj[6]), u2b(mi[6])));
    __nv_bfloat162 d7 = __habs2(__hsub2(u2b(mj[7]), u2b(mi[7])));
    __nv_bfloat162 s = __hadd2(__hadd2(__hadd2(d0, d1), __hadd2(d2, d3)),
                               __hadd2(__hadd2(d4, d5), __hadd2(d6, d7)));
    uint32_t u = b2u(s);
    float lo = __uint_as_float(u << 16);          // bf16 -> f32 is zero-extension: exact
    float hi = __uint_as_float(u & 0xFFFF0000u);
    return lo + hi;
}

// ---------------------------------------------------------------------------
// Conversion kernels
// ---------------------------------------------------------------------------
__global__ __launch_bounds__(256)
void convert_x_kernel(const float* __restrict__ x) {
    int t = blockIdx.x * 256 + threadIdx.x;     // handles 8 floats
    const float4* src = reinterpret_cast<const float4*>(x) + 2 * (size_t)t;
    float4 a = src[0], b = src[1];
    __nv_bfloat162 p0 = __float22bfloat162_rn(make_float2(a.x, a.y));
    __nv_bfloat162 p1 = __float22bfloat162_rn(make_float2(a.z, a.w));
    __nv_bfloat162 p2 = __float22bfloat162_rn(make_float2(b.x, b.y));
    __nv_bfloat162 p3 = __float22bfloat162_rn(make_float2(b.z, b.w));
    uint4 out;
    out.x = b2u(p0); out.y = b2u(p1); out.z = b2u(p2); out.w = b2u(p3);
    reinterpret_cast<uint4*>(g_xb)[t] = out;
}

__global__ __launch_bounds__(256)
void convert_W_kernel(const float* __restrict__ W) {
    __shared__ float tile[32][33];
    const int n0 = blockIdx.x * 32;
    const int k0 = blockIdx.y * 32;
    const int tx = threadIdx.x & 31;
    const int ty = threadIdx.x >> 5;            // 0..7
#pragma unroll
    for (int r = 0; r < 4; r++)
        tile[ty + 8 * r][tx] = W[(size_t)(k0 + ty + 8 * r) * AA + n0 + tx];
    __syncthreads();
#pragma unroll
    for (int r = 0; r < 4; r++) {
        int n = n0 + ty + 8 * r;
        g_Wb[(size_t)n * AA + k0 + tx] = __float2bfloat16(tile[tx][ty + 8 * r]);
    }
}

// ---------------------------------------------------------------------------
// GEMM via mma.sync bf16 m16n8k16. Block 64x64, 128 threads (4 warps 2x2),
// K chunked by 64, swizzled smem, register prefetch. Epilogue -> bf16 g_Mb.
// ---------------------------------------------------------------------------
#define BK 64
#define NCH (AA / BK)   // 16

__global__ __launch_bounds__(128)
void gemm_mma_kernel() {
    __shared__ __align__(1024) __nv_bfloat16 sA[64 * BK];   // 8 KB
    __shared__ __align__(1024) __nv_bfloat16 sB[64 * BK];   // 8 KB

    const int tid = threadIdx.x;
    const int wid = tid >> 5;
    const int l   = tid & 31;
    const int mw  = wid & 1;
    const int nw  = wid >> 1;
    const int row0 = blockIdx.y * 64;
    const int col0 = blockIdx.x * 64;

    const uint32_t sA_addr = smem_u32(sA);
    const uint32_t sB_addr = smem_u32(sB);

    float acc[2][4][4];
#pragma unroll
    for (int mt = 0; mt < 2; mt++)
#pragma unroll
        for (int nt = 0; nt < 4; nt++)
#pragma unroll
            for (int e = 0; e < 4; e++) acc[mt][nt][e] = 0.0f;

    uint4 pa[4], pb[4];
#pragma unroll
    for (int s = 0; s < 4; s++) {
        int ch = tid + s * 128;
        int r = ch >> 3, u = ch & 7;
        pa[s] = *reinterpret_cast<const uint4*>(g_xb + (size_t)(row0 + r) * AA + u * 8);
        pb[s] = *reinterpret_cast<const uint4*>(g_Wb + (size_t)(col0 + r) * AA + u * 8);
    }

    const int aRow0 = ((l >> 3) & 1) * 8 + (l & 7) + mw * 32;
    const int bRow0 = nw * 32 + ((l >> 4) << 3) + (l & 7);
    const int aKsel = (l >> 4);
    const int bKsel = ((l >> 3) & 1);
    const int swz   = (l & 7);

    for (int c = 0; c < NCH; c++) {
#pragma unroll
        for (int s = 0; s < 4; s++) {
            int ch = tid + s * 128;
            int r = ch >> 3, u = ch & 7;
            uint32_t off = (uint32_t)(r * 128 + ((u ^ (r & 7)) << 4));
            *reinterpret_cast<uint4*>(reinterpret_cast<char*>(sA) + off) = pa[s];
            *reinterpret_cast<uint4*>(reinterpret_cast<char*>(sB) + off) = pb[s];
        }
        __syncthreads();

        if (c + 1 < NCH) {
            int k0 = (c + 1) * BK;
#pragma unroll
            for (int s = 0; s < 4; s++) {
                int ch = tid + s * 128;
                int r = ch >> 3, u = ch & 7;
                pa[s] = *reinterpret_cast<const uint4*>(g_xb + (size_t)(row0 + r) * AA + k0 + u * 8);
                pb[s] = *reinterpret_cast<const uint4*>(g_Wb + (size_t)(col0 + r) * AA + k0 + u * 8);
            }
        }

#pragma unroll
        for (int ks = 0; ks < 4; ks++) {
            uint32_t af[2][4], bf[4][2];
#pragma unroll
            for (int mt = 0; mt < 2; mt++) {
                int row = aRow0 + mt * 16;
                uint32_t u = (uint32_t)(ks * 2 + aKsel);
                uint32_t addr = sA_addr + (uint32_t)(row * 128) + (((u ^ swz)) << 4);
                LDMATRIX_X4(af[mt][0], af[mt][1], af[mt][2], af[mt][3], addr);
            }
#pragma unroll
            for (int ng = 0; ng < 2; ng++) {
                int row = bRow0 + ng * 16;
                uint32_t u = (uint32_t)(ks * 2 + bKsel);
                uint32_t addr = sB_addr + (uint32_t)(row * 128) + (((u ^ swz)) << 4);
                uint32_t r0, r1, r2, r3;
                LDMATRIX_X4(r0, r1, r2, r3, addr);
                bf[ng * 2 + 0][0] = r0; bf[ng * 2 + 0][1] = r1;
                bf[ng * 2 + 1][0] = r2; bf[ng * 2 + 1][1] = r3;
            }
#pragma unroll
            for (int mt = 0; mt < 2; mt++)
#pragma unroll
                for (int nt = 0; nt < 4; nt++)
                    mma_bf16(acc[mt][nt], af[mt], bf[nt]);
        }
        __syncthreads();
    }

    // Epilogue: bf16x2 into pairwise layout g_Mb[row*512 + b*8 + c2]
    const int g = l >> 2;
    const int cc2 = (l & 3) * 2;
#pragma unroll
    for (int mt = 0; mt < 2; mt++) {
#pragma unroll
        for (int nt = 0; nt < 4; nt++) {
            int gcol = col0 + nw * 32 + nt * 8 + cc2;
            int b  = gcol >> 4;
            int c2 = (gcol & 15) >> 1;
            int rowA = row0 + mw * 32 + mt * 16 + g;
            __nv_bfloat162 v0 = __float22bfloat162_rn(
                make_float2(acc[mt][nt][0], acc[mt][nt][1]));
            __nv_bfloat162 v1 = __float22bfloat162_rn(
                make_float2(acc[mt][nt][2], acc[mt][nt][3]));
            g_Mb[(size_t)rowA * 512 + b * 8 + c2]       = b2u(v0);
            g_Mb[(size_t)(rowA + 8) * 512 + b * 8 + c2] = b2u(v1);
        }
    }
}

// ---------------------------------------------------------------------------
// Pairwise, triangular tiles over 32 groups of 16 rows. 528 blocks x 256 thr.
// Thread (b = t&63, isp = t>>6): owns 4 i-rows, loops 16 j-rows.
// i-side written directly (unique per thread); j-side pre-reduced in smem.
// ---------------------------------------------------------------------------
__global__ __launch_bounds__(256)
void pairwise_kernel() {
    const int t   = threadIdx.x;
    const int b   = t & 63;
    const int isp = t >> 6;        // 0..3

    // decode triangular tile: offset(g) = g*(65-g)/2
    int tt = blockIdx.x;
    int gi = (int)(32.5f - sqrtf(32.5f * 32.5f - 2.0f * (float)tt));
    if (gi < 0) gi = 0; if (gi > 31) gi = 31;
    while (gi > 0 && (gi * (65 - gi)) / 2 > tt) gi--;
    while (((gi + 1) * (65 - (gi + 1))) / 2 <= tt) gi++;
    int gj = gi + (tt - (gi * (65 - gi)) / 2);

    const int i0 = gi * GSZ + isp * 4;
    const int j0 = gj * GSZ;

    __shared__ float red[GSZ][4][BB];

    const uint4* Mb4 = reinterpret_cast<const uint4*>(g_Mb);

    // load 4 i-rows (8 u32 each)
    uint32_t mi[4][8];
#pragma unroll
    for (int k = 0; k < 4; k++) {
        uint4 v0 = Mb4[(size_t)(i0 + k) * 128 + b * 2];
        uint4 v1 = Mb4[(size_t)(i0 + k) * 128 + b * 2 + 1];
        mi[k][0] = v0.x; mi[k][1] = v0.y; mi[k][2] = v0.z; mi[k][3] = v0.w;
        mi[k][4] = v1.x; mi[k][5] = v1.y; mi[k][6] = v1.z; mi[k][7] = v1.w;
    }

    float acc_i[4] = {0.f, 0.f, 0.f, 0.f};

    uint4 p0 = Mb4[(size_t)j0 * 128 + b * 2];
    uint4 p1 = Mb4[(size_t)j0 * 128 + b * 2 + 1];

#pragma unroll 2
    for (int jj = 0; jj < GSZ; jj++) {
        uint4 c0 = p0, c1 = p1;
        if (jj + 1 < GSZ) {
            p0 = Mb4[(size_t)(j0 + jj + 1) * 128 + b * 2];
            p1 = Mb4[(size_t)(j0 + jj + 1) * 128 + b * 2 + 1];
        }
        uint32_t mj[8] = {c0.x, c0.y, c0.z, c0.w, c1.x, c1.y, c1.z, c1.w};

        float ej = 0.0f;
#pragma unroll
        for (int k = 0; k < 4; k++) {
            float s = l1_16(mj, mi[k]);
            float e = exp2f(s * -1.44269504f);
            acc_i[k] += e;
            ej += e;
        }
        red[jj][isp][b] = ej;
    }

    // i-side: unique slot per thread (src = gj)
#pragma unroll
    for (int k = 0; k < 4; k++)
        g_Pp[gj][(size_t)(i0 + k) * BB + b] = acc_i[k];

    __syncthreads();

    // j-side: only for off-diagonal tiles (src = gi)
    if (gi != gj) {
#pragma unroll
        for (int w = 0; w < 4; w++) {
            int cell = t + w * 256;           // 0..1023
            int jj = cell >> 6;
            int bb = cell & 63;
            float s = red[jj][0][bb] + red[jj][1][bb] + red[jj][2][bb] + red[jj][3][bb];
            g_Pp[gi][(size_t)(j0 + jj) * BB + bb] = s;
        }
    }
}

// ---------------------------------------------------------------------------
// Combine: out[:, :1024] = x ; out[:, 1024+b] = sum_src g_Pp[src][i][b] - 1
// ---------------------------------------------------------------------------
__global__ __launch_bounds__(256)
void combine_kernel(const float* __restrict__ x, float* __restrict__ out) {
    const int i = blockIdx.x;
    const int t = threadIdx.x;
    float4 v = reinterpret_cast<const float4*>(x + (size_t)i * AA)[t];
    reinterpret_cast<float4*>(out + (size_t)i * OUTW)[t] = v;
    if (t < BB) {
        float s = -1.0f;
#pragma unroll
        for (int src = 0; src < NGRP; src++)
            s += g_Pp[src][(size_t)i * BB + t];
        out[(size_t)i * OUTW + AA + t] = s;
    }
}

// ---------------------------------------------------------------------------
extern "C" void kernel_launch(void* const* d_in, const int* in_sizes, int n_in,
                              void* d_out, int out_size) {
    const float* x = (const float*)d_in[0];   // (512, 1024)
    const float* T = (const float*)d_in[1];   // (1024, 1024)
    float* out = (float*)d_out;               // (512, 1088)

    convert_x_kernel<<<NN * AA / (256 * 8), 256>>>(x);   // 256 blocks
    dim3 wgrid(AA / 32, AA / 32);                         // (32, 32)
    convert_W_kernel<<<wgrid, 256>>>(T);

    dim3 ggrid(AA / 64, NN / 64);                         // (16, 8) = 128 blocks
    gemm_mma_kernel<<<ggrid, 128>>>();

    pairwise_kernel<<<NTILES, 256>>>();                   // 528 blocks

    combine_kernel<<<NN, 256>>>(x, out);
}

// round 6
// speedup vs baseline: 2.9728x; 1.1160x over previous
#include <cuda_runtime.h>
#include <cuda_bf16.h>
#include <cstdint>

// Problem constants: N=512, A=1024, B=64, C=16
#define NN   512
#define AA   1024
#define BB   64
#define CC   16
#define OUTW (AA + BB)   // 1088

#define NGRP   32            // row groups of 16
#define GSZ    16
#define NTILES (NGRP * (NGRP + 1) / 2)   // 528

#define LOG2E 1.44269504088896340736f

// ---------------- device scratch ----------------
// M (pre-scaled by log2e) in bf16x2: g_Mb[row*512 + b*8 + c2]
__device__ uint32_t g_Mb[NN * 512];
// partial sums: g_Pp[src_group][row][b]; every slot written exactly once
__device__ float g_Pp[NGRP][NN * BB];
__device__ __nv_bfloat16 g_xb[NN * AA];     // x in bf16
__device__ __nv_bfloat16 g_Wb[AA * AA];     // W^T * log2e in bf16: g_Wb[n][k]

// ---------------- helpers ----------------
__device__ __forceinline__ uint32_t smem_u32(const void* p) {
    uint32_t a;
    asm("{ .reg .u64 t; cvta.to.shared.u64 t, %1; cvt.u32.u64 %0, t; }" : "=r"(a) : "l"(p));
    return a;
}
#define LDMATRIX_X4(r0, r1, r2, r3, addr) \
    asm volatile("ldmatrix.sync.aligned.m8n8.x4.shared.b16 {%0,%1,%2,%3}, [%4];" \
        : "=r"(r0), "=r"(r1), "=r"(r2), "=r"(r3) : "r"(addr))

__device__ __forceinline__ void mma_bf16(float d[4], const uint32_t a[4], const uint32_t b[2]) {
    asm volatile(
        "mma.sync.aligned.m16n8k16.row.col.f32.bf16.bf16.f32 "
        "{%0,%1,%2,%3}, {%4,%5,%6,%7}, {%8,%9}, {%0,%1,%2,%3};"
        : "+f"(d[0]), "+f"(d[1]), "+f"(d[2]), "+f"(d[3])
        : "r"(a[0]), "r"(a[1]), "r"(a[2]), "r"(a[3]), "r"(b[0]), "r"(b[1]));
}

__device__ __forceinline__ __nv_bfloat162 u2b(uint32_t u) {
    return *reinterpret_cast<__nv_bfloat162*>(&u);
}
__device__ __forceinline__ uint32_t b2u(__nv_bfloat162 v) {
    return *reinterpret_cast<uint32_t*>(&v);
}
__device__ __forceinline__ float ex2(float v) {
    float r; asm("ex2.approx.f32 %0, %1;" : "=f"(r) : "f"(v)); return r;
}

// -(L1 over 16 bf16 components held as 8 bf16x2 regs); exact lo/hi extraction.
__device__ __forceinline__ float l1_neg(const uint32_t* mj, const uint32_t* mi) {
    __nv_bfloat162 d0 = __habs2(__hsub2(u2b(mj[0]), u2b(mi[0])));
    __nv_bfloat162 d1 = __habs2(__hsub2(u2b(mj[1]), u2b(mi[1])));
    __nv_bfloat162 d2 = __habs2(__hsub2(u2b(mj[2]), u2b(mi[2])));
    __nv_bfloat162 d3 = __habs2(__hsub2(u2b(mj[3]), u2b(mi[3])));
    __nv_bfloat162 d4 = __habs2(__hsub2(u2b(mj[4]), u2b(mi[4])));
    __nv_bfloat162 d5 = __habs2(__hsub2(u2b(mj[5]), u2b(mi[5])));
    __nv_bfloat162 d6 = __habs2(__hsub2(u2b(mj[6]), u2b(mi[6])));
    __nv_bfloat162 d7 = __habs2(__hsub2(u2b(mj[7]), u2b(mi[7])));
    __nv_bfloat162 s = __hadd2(__hadd2(__hadd2(d0, d1), __hadd2(d2, d3)),
                               __hadd2(__hadd2(d4, d5), __hadd2(d6, d7)));
    uint32_t u = b2u(s);
    float lo = __uint_as_float(u << 16);          // bf16 -> f32 zero-extension: exact
    float hi = __uint_as_float(u & 0xFFFF0000u);
    return (-lo) - hi;                            // FADD with neg modifiers
}

// ---------------------------------------------------------------------------
// Fused prep: blocks [0,256): copy x -> out and convert x -> g_xb (bf16).
//             blocks [256,1280): transpose+scale W -> g_Wb (bf16).
// ---------------------------------------------------------------------------
__global__ __launch_bounds__(256)
void prep_kernel(const float* __restrict__ x, const float* __restrict__ W,
                 float* __restrict__ out) {
    if (blockIdx.x < 256) {
        int t = blockIdx.x * 256 + threadIdx.x;     // handles 8 floats
        int row  = t >> 7;
        int col8 = (t & 127) * 8;
        const float4* src = reinterpret_cast<const float4*>(x + (size_t)row * AA + col8);
        float4 a = src[0], b = src[1];
        // copy to out
        float4* dst = reinterpret_cast<float4*>(out + (size_t)row * OUTW + col8);
        dst[0] = a; dst[1] = b;
        // convert to bf16
        __nv_bfloat162 p0 = __float22bfloat162_rn(make_float2(a.x, a.y));
        __nv_bfloat162 p1 = __float22bfloat162_rn(make_float2(a.z, a.w));
        __nv_bfloat162 p2 = __float22bfloat162_rn(make_float2(b.x, b.y));
        __nv_bfloat162 p3 = __float22bfloat162_rn(make_float2(b.z, b.w));
        uint4 o; o.x = b2u(p0); o.y = b2u(p1); o.z = b2u(p2); o.w = b2u(p3);
        reinterpret_cast<uint4*>(g_xb)[t] = o;
    } else {
        __shared__ float tile[32][33];
        int idx = blockIdx.x - 256;                 // 0..1023
        const int n0 = (idx & 31) * 32;
        const int k0 = (idx >> 5) * 32;
        const int tx = threadIdx.x & 31;
        const int ty = threadIdx.x >> 5;            // 0..7
#pragma unroll
        for (int r = 0; r < 4; r++)
            tile[ty + 8 * r][tx] = W[(size_t)(k0 + ty + 8 * r) * AA + n0 + tx];
        __syncthreads();
#pragma unroll
        for (int r = 0; r < 4; r++) {
            int n = n0 + ty + 8 * r;
            g_Wb[(size_t)n * AA + k0 + tx] =
                __float2bfloat16(tile[tx][ty + 8 * r] * LOG2E);
        }
    }
}

// ---------------------------------------------------------------------------
// GEMM via mma.sync bf16 m16n8k16. Block 64x64, 128 threads (4 warps 2x2),
// K chunked by 64, swizzled smem, register prefetch. Epilogue -> bf16 g_Mb.
// ---------------------------------------------------------------------------
#define BK 64
#define NCH (AA / BK)   // 16

__global__ __launch_bounds__(128)
void gemm_mma_kernel() {
    __shared__ __align__(1024) __nv_bfloat16 sA[64 * BK];   // 8 KB
    __shared__ __align__(1024) __nv_bfloat16 sB[64 * BK];   // 8 KB

    const int tid = threadIdx.x;
    const int wid = tid >> 5;
    const int l   = tid & 31;
    const int mw  = wid & 1;
    const int nw  = wid >> 1;
    const int row0 = blockIdx.y * 64;
    const int col0 = blockIdx.x * 64;

    const uint32_t sA_addr = smem_u32(sA);
    const uint32_t sB_addr = smem_u32(sB);

    float acc[2][4][4];
#pragma unroll
    for (int mt = 0; mt < 2; mt++)
#pragma unroll
        for (int nt = 0; nt < 4; nt++)
#pragma unroll
            for (int e = 0; e < 4; e++) acc[mt][nt][e] = 0.0f;

    uint4 pa[4], pb[4];
#pragma unroll
    for (int s = 0; s < 4; s++) {
        int ch = tid + s * 128;
        int r = ch >> 3, u = ch & 7;
        pa[s] = *reinterpret_cast<const uint4*>(g_xb + (size_t)(row0 + r) * AA + u * 8);
        pb[s] = *reinterpret_cast<const uint4*>(g_Wb + (size_t)(col0 + r) * AA + u * 8);
    }

    const int aRow0 = ((l >> 3) & 1) * 8 + (l & 7) + mw * 32;
    const int bRow0 = nw * 32 + ((l >> 4) << 3) + (l & 7);
    const int aKsel = (l >> 4);
    const int bKsel = ((l >> 3) & 1);
    const int swz   = (l & 7);

    for (int c = 0; c < NCH; c++) {
#pragma unroll
        for (int s = 0; s < 4; s++) {
            int ch = tid + s * 128;
            int r = ch >> 3, u = ch & 7;
            uint32_t off = (uint32_t)(r * 128 + ((u ^ (r & 7)) << 4));
            *reinterpret_cast<uint4*>(reinterpret_cast<char*>(sA) + off) = pa[s];
            *reinterpret_cast<uint4*>(reinterpret_cast<char*>(sB) + off) = pb[s];
        }
        __syncthreads();

        if (c + 1 < NCH) {
            int k0 = (c + 1) * BK;
#pragma unroll
            for (int s = 0; s < 4; s++) {
                int ch = tid + s * 128;
                int r = ch >> 3, u = ch & 7;
                pa[s] = *reinterpret_cast<const uint4*>(g_xb + (size_t)(row0 + r) * AA + k0 + u * 8);
                pb[s] = *reinterpret_cast<const uint4*>(g_Wb + (size_t)(col0 + r) * AA + k0 + u * 8);
            }
        }

#pragma unroll
        for (int ks = 0; ks < 4; ks++) {
            uint32_t af[2][4], bf[4][2];
#pragma unroll
            for (int mt = 0; mt < 2; mt++) {
                int row = aRow0 + mt * 16;
                uint32_t u = (uint32_t)(ks * 2 + aKsel);
                uint32_t addr = sA_addr + (uint32_t)(row * 128) + (((u ^ swz)) << 4);
                LDMATRIX_X4(af[mt][0], af[mt][1], af[mt][2], af[mt][3], addr);
            }
#pragma unroll
            for (int ng = 0; ng < 2; ng++) {
                int row = bRow0 + ng * 16;
                uint32_t u = (uint32_t)(ks * 2 + bKsel);
                uint32_t addr = sB_addr + (uint32_t)(row * 128) + (((u ^ swz)) << 4);
                uint32_t r0, r1, r2, r3;
                LDMATRIX_X4(r0, r1, r2, r3, addr);
                bf[ng * 2 + 0][0] = r0; bf[ng * 2 + 0][1] = r1;
                bf[ng * 2 + 1][0] = r2; bf[ng * 2 + 1][1] = r3;
            }
#pragma unroll
            for (int mt = 0; mt < 2; mt++)
#pragma unroll
                for (int nt = 0; nt < 4; nt++)
                    mma_bf16(acc[mt][nt], af[mt], bf[nt]);
        }
        __syncthreads();
    }

    // Epilogue: bf16x2 into pairwise layout g_Mb[row*512 + b*8 + c2]
    const int g = l >> 2;
    const int cc2 = (l & 3) * 2;
#pragma unroll
    for (int mt = 0; mt < 2; mt++) {
#pragma unroll
        for (int nt = 0; nt < 4; nt++) {
            int gcol = col0 + nw * 32 + nt * 8 + cc2;
            int b  = gcol >> 4;
            int c2 = (gcol & 15) >> 1;
            int rowA = row0 + mw * 32 + mt * 16 + g;
            __nv_bfloat162 v0 = __float22bfloat162_rn(
                make_float2(acc[mt][nt][0], acc[mt][nt][1]));
            __nv_bfloat162 v1 = __float22bfloat162_rn(
                make_float2(acc[mt][nt][2], acc[mt][nt][3]));
            g_Mb[(size_t)rowA * 512 + b * 8 + c2]       = b2u(v0);
            g_Mb[(size_t)(rowA + 8) * 512 + b * 8 + c2] = b2u(v1);
        }
    }
}

// ---------------------------------------------------------------------------
// Pairwise, triangular tiles over 32 groups of 16 rows. 528 blocks x 256 thr.
// Thread (b = t&63, isp = t>>6): owns 4 i-rows, loops 16 j-rows.
// Prefetch depth 2 on j-rows to cover L2 latency.
// ---------------------------------------------------------------------------
__global__ __launch_bounds__(256)
void pairwise_kernel() {
    const int t   = threadIdx.x;
    const int b   = t & 63;
    const int isp = t >> 6;        // 0..3

    // decode triangular tile: offset(g) = g*(65-g)/2
    int tt = blockIdx.x;
    int gi = (int)(32.5f - sqrtf(32.5f * 32.5f - 2.0f * (float)tt));
    if (gi < 0) gi = 0; if (gi > 31) gi = 31;
    while (gi > 0 && (gi * (65 - gi)) / 2 > tt) gi--;
    while (((gi + 1) * (65 - (gi + 1))) / 2 <= tt) gi++;
    int gj = gi + (tt - (gi * (65 - gi)) / 2);

    const int i0 = gi * GSZ + isp * 4;
    const int j0 = gj * GSZ;

    __shared__ float red[GSZ][4][BB];

    const uint4* Mb4 = reinterpret_cast<const uint4*>(g_Mb);

    // load 4 i-rows (8 u32 each)
    uint32_t mi[4][8];
#pragma unroll
    for (int k = 0; k < 4; k++) {
        uint4 v0 = Mb4[(size_t)(i0 + k) * 128 + b * 2];
        uint4 v1 = Mb4[(size_t)(i0 + k) * 128 + b * 2 + 1];
        mi[k][0] = v0.x; mi[k][1] = v0.y; mi[k][2] = v0.z; mi[k][3] = v0.w;
        mi[k][4] = v1.x; mi[k][5] = v1.y; mi[k][6] = v1.z; mi[k][7] = v1.w;
    }

    float acc_i[4] = {0.f, 0.f, 0.f, 0.f};

    // prefetch depth 2 on j-rows
    uint32_t jb[2][8];
#pragma unroll
    for (int p = 0; p < 2; p++) {
        uint4 v0 = Mb4[(size_t)(j0 + p) * 128 + b * 2];
        uint4 v1 = Mb4[(size_t)(j0 + p) * 128 + b * 2 + 1];
        jb[p][0] = v0.x; jb[p][1] = v0.y; jb[p][2] = v0.z; jb[p][3] = v0.w;
        jb[p][4] = v1.x; jb[p][5] = v1.y; jb[p][6] = v1.z; jb[p][7] = v1.w;
    }

#pragma unroll
    for (int jj = 0; jj < GSZ; jj++) {
        uint32_t mj[8];
#pragma unroll
        for (int c = 0; c < 8; c++) mj[c] = jb[jj & 1][c];
        if (jj + 2 < GSZ) {
            uint4 v0 = Mb4[(size_t)(j0 + jj + 2) * 128 + b * 2];
            uint4 v1 = Mb4[(size_t)(j0 + jj + 2) * 128 + b * 2 + 1];
            jb[jj & 1][0] = v0.x; jb[jj & 1][1] = v0.y;
            jb[jj & 1][2] = v0.z; jb[jj & 1][3] = v0.w;
            jb[jj & 1][4] = v1.x; jb[jj & 1][5] = v1.y;
            jb[jj & 1][6] = v1.z; jb[jj & 1][7] = v1.w;
        }

        float ej = 0.0f;
#pragma unroll
        for (int k = 0; k < 4; k++) {
            float e = ex2(l1_neg(mj, mi[k]));
            acc_i[k] += e;
            ej += e;
        }
        red[jj][isp][b] = ej;
    }

    // i-side: unique slot per thread (src = gj)
#pragma unroll
    for (int k = 0; k < 4; k++)
        g_Pp[gj][(size_t)(i0 + k) * BB + b] = acc_i[k];

    __syncthreads();

    // j-side: only for off-diagonal tiles (src = gi)
    if (gi != gj) {
#pragma unroll
        for (int w = 0; w < 4; w++) {
            int cell = t + w * 256;           // 0..1023
            int jj = cell >> 6;
            int bb = cell & 63;
            float s = red[jj][0][bb] + red[jj][1][bb] + red[jj][2][bb] + red[jj][3][bb];
            g_Pp[gi][(size_t)(j0 + jj) * BB + bb] = s;
        }
    }
}

// ---------------------------------------------------------------------------
// Combine: out[:, 1024+b] = sum_src g_Pp[src][i][b] - 1   (x already copied)
// ---------------------------------------------------------------------------
__global__ __launch_bounds__(512)
void combine_kernel(float* __restrict__ out) {
    int idx = blockIdx.x * 512 + threadIdx.x;   // 0..32767
    int i = idx >> 6;
    int b = idx & 63;
    float s = -1.0f;
#pragma unroll
    for (int src = 0; src < NGRP; src++)
        s += g_Pp[src][(size_t)i * BB + b];
    out[(size_t)i * OUTW + AA + b] = s;
}

// ---------------------------------------------------------------------------
extern "C" void kernel_launch(void* const* d_in, const int* in_sizes, int n_in,
                              void* d_out, int out_size) {
    const float* x = (const float*)d_in[0];   // (512, 1024)
    const float* T = (const float*)d_in[1];   // (1024, 1024)
    float* out = (float*)d_out;               // (512, 1088)

    prep_kernel<<<1280, 256>>>(x, T, out);

    dim3 ggrid(AA / 64, NN / 64);             // (16, 8) = 128 blocks
    gemm_mma_kernel<<<ggrid, 128>>>();

    pairwise_kernel<<<NTILES, 256>>>();       // 528 blocks

    combine_kernel<<<64, 512>>>(out);
}